// round 9
// baseline (speedup 1.0000x reference)
#include <cuda_runtime.h>

#define B_ 8
#define S_ 4096
#define D_ 512
#define F_ 2048
#define E_ 8
#define NSPLIT 32

// ---------------- scratch (device globals; no allocation allowed) ----------
__device__ float g_H[(size_t)B_ * S_ * F_];          // 268 MB: gh (first 64MB) then FFN hidden
__device__ float g_ghpart[B_][NSPLIT][D_];           // gate column-sum partials
__device__ float g_gate[B_][E_];                     // g[b][e]
__device__ float g_W1m[(size_t)B_ * F_ * D_];        // merged W1 per batch
__device__ float g_b1m[B_ * F_];
__device__ float g_W2m[(size_t)B_ * D_ * F_];        // merged W2 per batch
__device__ float g_b2m[B_ * D_];
__device__ float g_lng[D_];
__device__ float g_lnb[D_];

// ---------------- tf32 helpers --------------------------------------------
__device__ __forceinline__ unsigned f2tf(float x) {
    unsigned u;
    asm("cvt.rna.tf32.f32 %0, %1;" : "=r"(u) : "f"(x));
    return u;
}

// ---------------- tiled tf32 tensor-core GEMM ------------------------------
// C[M,N] = act(A[M,K] @ B[N,K]^T + bias[N]), row-major, batched via blockIdx.z.
// BM=BN=128, BK=32, 256 threads (8 warps as 2x4), warp tile 64x32,
// per-warp 4x4 m16n8k8 fragments. All problem dims divide tiles exactly.
#define BM 128
#define BN 128
#define BK 32
#define SA 36   // padded smem stride (words): conflict-free & 16B-aligned

template <bool RELU>
__global__ void __launch_bounds__(256, 2)
gemm_tf32(const float* __restrict__ A, long sA,
          const float* __restrict__ Bw, long sB,
          const float* __restrict__ bias, long sBias,
          float* __restrict__ C, long sC,
          int M, int N, int K)
{
    __shared__ unsigned As[BM][SA];
    __shared__ unsigned Bs[BN][SA];

    const int bz = blockIdx.z;
    A   += (long)bz * sA;
    Bw  += (long)bz * sB;
    C   += (long)bz * sC;
    const float* bvec = bias + (long)bz * sBias;

    const int m0 = blockIdx.y * BM;
    const int n0 = blockIdx.x * BN;

    const int tid  = threadIdx.x;
    const int warp = tid >> 5;
    const int lane = tid & 31;
    const int gid  = lane >> 2;   // group id 0..7
    const int tig  = lane & 3;    // thread-in-group 0..3
    const int wm   = warp >> 2;   // 0..1  (rows of 64)
    const int wn   = warp & 3;    // 0..3  (cols of 32)

    float acc[4][4][4];
#pragma unroll
    for (int i = 0; i < 4; i++)
#pragma unroll
        for (int j = 0; j < 4; j++) {
            acc[i][j][0] = 0.f; acc[i][j][1] = 0.f;
            acc[i][j][2] = 0.f; acc[i][j][3] = 0.f;
        }

    for (int kt = 0; kt < K; kt += BK) {
        __syncthreads();
        // load 128x32 A-tile and 128x32 B-tile (4 float4 per thread each)
#pragma unroll
        for (int it = 0; it < 4; it++) {
            int idx = tid + it * 256;
            int r = idx >> 3;
            int c = (idx & 7) << 2;
            float4 va = *(const float4*)(A + (long)(m0 + r) * K + kt + c);
            unsigned* da = &As[r][c];
            da[0] = f2tf(va.x); da[1] = f2tf(va.y);
            da[2] = f2tf(va.z); da[3] = f2tf(va.w);
            float4 vb = *(const float4*)(Bw + (long)(n0 + r) * K + kt + c);
            unsigned* db = &Bs[r][c];
            db[0] = f2tf(vb.x); db[1] = f2tf(vb.y);
            db[2] = f2tf(vb.z); db[3] = f2tf(vb.w);
        }
        __syncthreads();

#pragma unroll
        for (int kk = 0; kk < BK; kk += 8) {
            unsigned af[4][4], bf[4][2];
#pragma unroll
            for (int mf = 0; mf < 4; mf++) {
                int r = wm * 64 + mf * 16 + gid;
                af[mf][0] = As[r][kk + tig];
                af[mf][1] = As[r + 8][kk + tig];
                af[mf][2] = As[r][kk + tig + 4];
                af[mf][3] = As[r + 8][kk + tig + 4];
            }
#pragma unroll
            for (int nf = 0; nf < 4; nf++) {
                int n = wn * 32 + nf * 8 + gid;
                bf[nf][0] = Bs[n][kk + tig];
                bf[nf][1] = Bs[n][kk + tig + 4];
            }
#pragma unroll
            for (int mf = 0; mf < 4; mf++)
#pragma unroll
                for (int nf = 0; nf < 4; nf++) {
                    asm volatile(
                        "mma.sync.aligned.m16n8k8.row.col.f32.tf32.tf32.f32 "
                        "{%0,%1,%2,%3}, {%4,%5,%6,%7}, {%8,%9}, {%0,%1,%2,%3};\n"
                        : "+f"(acc[mf][nf][0]), "+f"(acc[mf][nf][1]),
                          "+f"(acc[mf][nf][2]), "+f"(acc[mf][nf][3])
                        : "r"(af[mf][0]), "r"(af[mf][1]),
                          "r"(af[mf][2]), "r"(af[mf][3]),
                          "r"(bf[nf][0]), "r"(bf[nf][1]));
                }
        }
    }

    // epilogue: bias (+relu), float2 stores
#pragma unroll
    for (int mf = 0; mf < 4; mf++) {
        int r0 = m0 + wm * 64 + mf * 16 + gid;
#pragma unroll
        for (int nf = 0; nf < 4; nf++) {
            int c0 = n0 + wn * 32 + nf * 8 + 2 * tig;
            float bb0 = bvec[c0];
            float bb1 = bvec[c0 + 1];
            float v0 = acc[mf][nf][0] + bb0;
            float v1 = acc[mf][nf][1] + bb1;
            float v2 = acc[mf][nf][2] + bb0;
            float v3 = acc[mf][nf][3] + bb1;
            if (RELU) {
                v0 = fmaxf(v0, 0.f); v1 = fmaxf(v1, 0.f);
                v2 = fmaxf(v2, 0.f); v3 = fmaxf(v3, 0.f);
            }
            *(float2*)(C + (long)r0 * N + c0)       = make_float2(v0, v1);
            *(float2*)(C + (long)(r0 + 8) * N + c0) = make_float2(v2, v3);
        }
    }
}

// ---------------- gate: column sum of gh over tokens -----------------------
__global__ void gate_colsum(const float* __restrict__ gh)
{
    int sp = blockIdx.x;          // 0..NSPLIT-1
    int b  = blockIdx.y;          // 0..B-1
    int h  = threadIdx.x;         // 0..511
    const int chunk = S_ / NSPLIT;
    const float* p = gh + ((long)b * S_ + (long)sp * chunk) * D_ + h;
    float s = 0.f;
#pragma unroll 8
    for (int i = 0; i < chunk; i++) s += p[(long)i * D_];
    g_ghpart[b][sp][h] = s;
}

// ---------------- gate: fc2 + mean -----------------------------------------
__global__ void gate_fc2(const float* __restrict__ g2w, const float* __restrict__ g2b)
{
    __shared__ float hs[D_];
    int b = blockIdx.x;
    for (int h = threadIdx.x; h < D_; h += 256) {
        float s = 0.f;
#pragma unroll
        for (int p = 0; p < NSPLIT; p++) s += g_ghpart[b][p][h];
        hs[h] = s;
    }
    __syncthreads();
    int w = threadIdx.x >> 5, l = threadIdx.x & 31;   // warp w -> expert w
    float s = 0.f;
    for (int h = l; h < D_; h += 32) s += hs[h] * g2w[w * D_ + h];
#pragma unroll
    for (int off = 16; off; off >>= 1) s += __shfl_xor_sync(0xffffffffu, s, off);
    if (l == 0) g_gate[b][w] = g2b[w] + s * (1.f / (float)S_);
}

// ---------------- merge: out[b][i] = base[i] + sum_e g[b][e]*tv[e][i] -------
__global__ void merge_kernel(const float* __restrict__ base, const float* __restrict__ tv,
                             float* __restrict__ out, int n4)
{
    __shared__ float gs[B_ * E_];
    if (threadIdx.x < B_ * E_) gs[threadIdx.x] = ((const float*)g_gate)[threadIdx.x];
    __syncthreads();
    const float4* b4 = (const float4*)base;
    const float4* t4 = (const float4*)tv;
    float4* o4 = (float4*)out;
    for (long i = (long)blockIdx.x * blockDim.x + threadIdx.x; i < n4;
         i += (long)gridDim.x * blockDim.x) {
        float4 t[E_];
#pragma unroll
        for (int e = 0; e < E_; e++) t[e] = t4[(long)e * n4 + i];
        float4 bb = b4[i];
#pragma unroll
        for (int b = 0; b < B_; b++) {
            float4 o = bb;
#pragma unroll
            for (int e = 0; e < E_; e++) {
                float ge = gs[b * E_ + e];
                o.x += ge * t[e].x; o.y += ge * t[e].y;
                o.z += ge * t[e].z; o.w += ge * t[e].w;
            }
            o4[(long)b * n4 + i] = o;
        }
    }
}

// ---------------- LN param merge (gate-independent) ------------------------
__global__ void ln_merge(const float* __restrict__ lg, const float* __restrict__ lb,
                         const float* __restrict__ tg, const float* __restrict__ tb)
{
    int d = blockIdx.x * blockDim.x + threadIdx.x;
    if (d >= D_) return;
    float sg = 0.f, sb = 0.f;
#pragma unroll
    for (int e = 0; e < E_; e++) { sg += tg[e * D_ + d]; sb += tb[e * D_ + d]; }
    g_lng[d] = lg[d] + 0.03f * (sg - (float)E_ * lg[d]);
    g_lnb[d] = lb[d] + 0.03f * (sb - (float)E_ * lb[d]);
}

// ---------------- residual + layernorm (in-place on d_out) -----------------
__global__ void ln_kernel(const float* __restrict__ x, float* __restrict__ out)
{
    long row = blockIdx.x;
    const float* xr = x + row * (long)D_;
    float* orow = out + row * (long)D_;
    int t = threadIdx.x;
    float v0 = xr[t] + orow[t];
    float v1 = xr[t + 256] + orow[t + 256];
    float s = v0 + v1, q = v0 * v0 + v1 * v1;
#pragma unroll
    for (int off = 16; off; off >>= 1) {
        s += __shfl_xor_sync(0xffffffffu, s, off);
        q += __shfl_xor_sync(0xffffffffu, q, off);
    }
    __shared__ float ss[8], sq[8];
    __shared__ float smu, sinv;
    int w = t >> 5, l = t & 31;
    if (l == 0) { ss[w] = s; sq[w] = q; }
    __syncthreads();
    if (t == 0) {
        float S = 0.f, Q = 0.f;
#pragma unroll
        for (int i = 0; i < 8; i++) { S += ss[i]; Q += sq[i]; }
        float mu = S * (1.f / (float)D_);
        float var = Q * (1.f / (float)D_) - mu * mu;
        smu = mu;
        sinv = rsqrtf(var + 1e-5f);
    }
    __syncthreads();
    float mu = smu, inv = sinv;
    orow[t]       = (v0 - mu) * inv * g_lng[t]       + g_lnb[t];
    orow[t + 256] = (v1 - mu) * inv * g_lng[t + 256] + g_lnb[t + 256];
}

// ---------------- launch ----------------------------------------------------
extern "C" void kernel_launch(void* const* d_in, const int* in_sizes, int n_in,
                              void* d_out, int out_size)
{
    const float* x      = (const float*)d_in[0];
    const float* gfc1_w = (const float*)d_in[1];
    const float* gfc1_b = (const float*)d_in[2];
    const float* gfc2_w = (const float*)d_in[3];
    const float* gfc2_b = (const float*)d_in[4];
    const float* W1     = (const float*)d_in[5];
    const float* b1     = (const float*)d_in[6];
    const float* W2     = (const float*)d_in[7];
    const float* b2     = (const float*)d_in[8];
    const float* ln_g   = (const float*)d_in[9];
    const float* ln_b   = (const float*)d_in[10];
    const float* tv_W1  = (const float*)d_in[11];
    const float* tv_b1  = (const float*)d_in[12];
    const float* tv_W2  = (const float*)d_in[13];
    const float* tv_b2  = (const float*)d_in[14];
    const float* tv_lng = (const float*)d_in[15];
    const float* tv_lnb = (const float*)d_in[16];
    float* out = (float*)d_out;

    float *H, *W1m, *b1m, *W2m, *b2m;
    cudaGetSymbolAddress((void**)&H,   g_H);
    cudaGetSymbolAddress((void**)&W1m, g_W1m);
    cudaGetSymbolAddress((void**)&b1m, g_b1m);
    cudaGetSymbolAddress((void**)&W2m, g_W2m);
    cudaGetSymbolAddress((void**)&b2m, g_b2m);

    // 1) gate fc1: gh = relu(x @ gfc1_w^T + b)   [32768, 512], stored in H
    gemm_tf32<true><<<dim3(D_ / BN, (B_ * S_) / BM, 1), 256>>>(
        x, 0, gfc1_w, 0, gfc1_b, 0, H, 0, B_ * S_, D_, D_);

    // 2) column sums + fc2 + mean -> g[b][e]
    gate_colsum<<<dim3(NSPLIT, B_), D_>>>(H);
    gate_fc2<<<B_, 256>>>(gfc2_w, gfc2_b);

    // 3) merged per-batch weights / biases / LN params
    merge_kernel<<<512, 256>>>(W1, tv_W1, W1m, (F_ * D_) / 4);
    merge_kernel<<<512, 256>>>(W2, tv_W2, W2m, (D_ * F_) / 4);
    merge_kernel<<<4,   256>>>(b1, tv_b1, b1m, F_ / 4);
    merge_kernel<<<2,   256>>>(b2, tv_b2, b2m, D_ / 4);
    ln_merge<<<2, 256>>>(ln_g, ln_b, tv_lng, tv_lnb);

    // 4) FFN1: H_b = relu(x_b @ W1m_b^T + b1m_b)   [4096, 2048] x 8
    gemm_tf32<true><<<dim3(F_ / BN, S_ / BM, B_), 256>>>(
        x, (long)S_ * D_, W1m, (long)F_ * D_, b1m, F_,
        H, (long)S_ * F_, S_, F_, D_);

    // 5) FFN2: out_b = H_b @ W2m_b^T + b2m_b       [4096, 512] x 8 (pre-LN)
    gemm_tf32<false><<<dim3(D_ / BN, S_ / BM, B_), 256>>>(
        H, (long)S_ * F_, W2m, (long)D_ * F_, b2m, D_,
        out, (long)S_ * D_, S_, D_, F_);

    // 6) residual + layernorm, in place on d_out
    ln_kernel<<<B_ * S_, 256>>>(x, out);
}

// round 10
// speedup vs baseline: 1.3838x; 1.3838x over previous
#include <cuda_runtime.h>

#define B_ 8
#define S_ 4096
#define D_ 512
#define F_ 2048
#define E_ 8
#define NSPLIT 32

// ---------------- scratch (device globals; no allocation allowed) ----------
__device__ float g_H[(size_t)B_ * S_ * F_];          // gh (first 64MB) then FFN hidden (tf32-rounded)
__device__ float g_xc[(size_t)B_ * S_ * D_];         // x pre-rounded to tf32
__device__ float g_gw1c[D_ * D_];                    // gfc1_w pre-rounded to tf32
__device__ float g_ghpart[B_][NSPLIT][D_];
__device__ float g_gate[B_][E_];
__device__ float g_W1m[(size_t)B_ * F_ * D_];        // merged W1 (tf32-rounded)
__device__ float g_b1m[B_ * F_];
__device__ float g_W2m[(size_t)B_ * D_ * F_];        // merged W2 (tf32-rounded)
__device__ float g_b2m[B_ * D_];
__device__ float g_lng[D_];
__device__ float g_lnb[D_];

// ---------------- tf32 helpers ---------------------------------------------
__device__ __forceinline__ unsigned f2tf(float x) {
    unsigned u;
    asm("cvt.rna.tf32.f32 %0, %1;" : "=r"(u) : "f"(x));
    return u;
}
__device__ __forceinline__ float rtf(float x) { return __uint_as_float(f2tf(x)); }

// ---------------- pipelined tf32 tensor-core GEMM --------------------------
// C[M,N] = act(A[M,K] @ B[N,K]^T + bias[N]); A,B already tf32-rounded fp32.
// BM=BN=128, BK=32, 256 thr (8 warps 2x4), warp tile 64x32, 4x4 m16n8k8.
// 3-stage cp.async pipeline, XOR-swizzled smem (conflict-free ld & st).
#define BM 128
#define BN 128
#define BK 32
#define STAGES 3
#define STAGE_WORDS (2 * BM * BK)   // As + Bs per stage (8192 words = 32KB)

template <bool RELU, bool CVT>
__global__ void __launch_bounds__(256, 2)
gemm_tf32(const float* __restrict__ A, long sAb,
          const float* __restrict__ Bw, long sBb,
          const float* __restrict__ bias, long sBias,
          float* __restrict__ C, long sC,
          int M, int N, int K)
{
    extern __shared__ unsigned sm[];

    const int bz = blockIdx.z;
    A  += (long)bz * sAb;
    Bw += (long)bz * sBb;
    C  += (long)bz * sC;
    const float* bvec = bias + (long)bz * sBias;

    const int m0 = blockIdx.y * BM;
    const int n0 = blockIdx.x * BN;

    const int tid  = threadIdx.x;
    const int warp = tid >> 5;
    const int lane = tid & 31;
    const int gid  = lane >> 2;
    const int tig  = lane & 3;
    const int wm   = warp >> 2;   // 0..1
    const int wn   = warp & 3;    // 0..3

    float acc[4][4][4];
#pragma unroll
    for (int i = 0; i < 4; i++)
#pragma unroll
        for (int j = 0; j < 4; j++)
#pragma unroll
            for (int q = 0; q < 4; q++) acc[i][j][q] = 0.f;

    const int KT = K / BK;

    // per-thread load coords: idx = tid + it*256 -> r = idx>>3, chunk c8 = idx&7
    auto load_stage = [&](int st, int kt) {
        unsigned* As = sm + st * STAGE_WORDS;
        unsigned* Bs = As + BM * BK;
#pragma unroll
        for (int it = 0; it < 4; it++) {
            int idx = tid + it * 256;
            int r = idx >> 3, c8 = idx & 7;
            int dst = r * BK + ((c8 ^ (r & 7)) << 2);
            unsigned sa = (unsigned)__cvta_generic_to_shared(As + dst);
            asm volatile("cp.async.cg.shared.global [%0], [%1], 16;\n"
                         :: "r"(sa), "l"(A + (long)(m0 + r) * K + kt + c8 * 4));
            unsigned sb = (unsigned)__cvta_generic_to_shared(Bs + dst);
            asm volatile("cp.async.cg.shared.global [%0], [%1], 16;\n"
                         :: "r"(sb), "l"(Bw + (long)(n0 + r) * K + kt + c8 * 4));
        }
    };

#pragma unroll
    for (int s = 0; s < STAGES - 1; s++) {
        load_stage(s, s * BK);
        asm volatile("cp.async.commit_group;\n");
    }

    for (int i = 0; i < KT; i++) {
        asm volatile("cp.async.wait_group %0;\n" :: "n"(STAGES - 2));
        __syncthreads();

        int nxt = i + STAGES - 1;
        if (nxt < KT) load_stage(nxt % STAGES, nxt * BK);
        asm volatile("cp.async.commit_group;\n");

        const unsigned* As = sm + (i % STAGES) * STAGE_WORDS;
        const unsigned* Bs = As + BM * BK;

#pragma unroll
        for (int kk = 0; kk < BK; kk += 8) {
            const int k4 = kk >> 2;
            unsigned af[4][4], bf[4][2];
            const int sw0 = ((k4 ^ gid) << 2) + tig;
            const int sw1 = (((k4 + 1) ^ gid) << 2) + tig;
#pragma unroll
            for (int mf = 0; mf < 4; mf++) {
                int r0 = (wm * 64 + mf * 16 + gid) * BK;
                af[mf][0] = As[r0 + sw0];
                af[mf][1] = As[r0 + 8 * BK + sw0];
                af[mf][2] = As[r0 + sw1];
                af[mf][3] = As[r0 + 8 * BK + sw1];
            }
#pragma unroll
            for (int nf = 0; nf < 4; nf++) {
                int nr = (wn * 32 + nf * 8 + gid) * BK;
                bf[nf][0] = Bs[nr + sw0];
                bf[nf][1] = Bs[nr + sw1];
            }
#pragma unroll
            for (int mf = 0; mf < 4; mf++)
#pragma unroll
                for (int nf = 0; nf < 4; nf++) {
                    asm volatile(
                        "mma.sync.aligned.m16n8k8.row.col.f32.tf32.tf32.f32 "
                        "{%0,%1,%2,%3}, {%4,%5,%6,%7}, {%8,%9}, {%0,%1,%2,%3};\n"
                        : "+f"(acc[mf][nf][0]), "+f"(acc[mf][nf][1]),
                          "+f"(acc[mf][nf][2]), "+f"(acc[mf][nf][3])
                        : "r"(af[mf][0]), "r"(af[mf][1]),
                          "r"(af[mf][2]), "r"(af[mf][3]),
                          "r"(bf[nf][0]), "r"(bf[nf][1]));
                }
        }
    }

    // epilogue: bias (+relu) (+tf32 rounding), float2 stores
#pragma unroll
    for (int mf = 0; mf < 4; mf++) {
        int r0 = m0 + wm * 64 + mf * 16 + gid;
#pragma unroll
        for (int nf = 0; nf < 4; nf++) {
            int c0 = n0 + wn * 32 + nf * 8 + 2 * tig;
            float bb0 = bvec[c0];
            float bb1 = bvec[c0 + 1];
            float v0 = acc[mf][nf][0] + bb0;
            float v1 = acc[mf][nf][1] + bb1;
            float v2 = acc[mf][nf][2] + bb0;
            float v3 = acc[mf][nf][3] + bb1;
            if (RELU) {
                v0 = fmaxf(v0, 0.f); v1 = fmaxf(v1, 0.f);
                v2 = fmaxf(v2, 0.f); v3 = fmaxf(v3, 0.f);
            }
            if (CVT) { v0 = rtf(v0); v1 = rtf(v1); v2 = rtf(v2); v3 = rtf(v3); }
            *(float2*)(C + (long)r0 * N + c0)       = make_float2(v0, v1);
            *(float2*)(C + (long)(r0 + 8) * N + c0) = make_float2(v2, v3);
        }
    }
}

// ---------------- tf32 pre-rounding copy ------------------------------------
__global__ void cvt_kernel(const float4* __restrict__ in, float4* __restrict__ out, long n4)
{
    for (long i = (long)blockIdx.x * blockDim.x + threadIdx.x; i < n4;
         i += (long)gridDim.x * blockDim.x) {
        float4 v = in[i];
        v.x = rtf(v.x); v.y = rtf(v.y); v.z = rtf(v.z); v.w = rtf(v.w);
        out[i] = v;
    }
}

// ---------------- gate: column sum of gh over tokens ------------------------
__global__ void gate_colsum(const float* __restrict__ gh)
{
    int sp = blockIdx.x, b = blockIdx.y, h = threadIdx.x;
    const int chunk = S_ / NSPLIT;
    const float* p = gh + ((long)b * S_ + (long)sp * chunk) * D_ + h;
    float s = 0.f;
#pragma unroll 8
    for (int i = 0; i < chunk; i++) s += p[(long)i * D_];
    g_ghpart[b][sp][h] = s;
}

// ---------------- gate: fc2 + mean ------------------------------------------
__global__ void gate_fc2(const float* __restrict__ g2w, const float* __restrict__ g2b)
{
    __shared__ float hs[D_];
    int b = blockIdx.x;
    for (int h = threadIdx.x; h < D_; h += 256) {
        float s = 0.f;
#pragma unroll
        for (int p = 0; p < NSPLIT; p++) s += g_ghpart[b][p][h];
        hs[h] = s;
    }
    __syncthreads();
    int w = threadIdx.x >> 5, l = threadIdx.x & 31;
    float s = 0.f;
    for (int h = l; h < D_; h += 32) s += hs[h] * g2w[w * D_ + h];
#pragma unroll
    for (int off = 16; off; off >>= 1) s += __shfl_xor_sync(0xffffffffu, s, off);
    if (l == 0) g_gate[b][w] = g2b[w] + s * (1.f / (float)S_);
}

// ---------------- merge: out[b][i] = base[i] + sum_e g[b][e]*tv[e][i] --------
__global__ void merge_kernel(const float* __restrict__ base, const float* __restrict__ tv,
                             float* __restrict__ out, int n4, int docvt)
{
    __shared__ float gs[B_ * E_];
    if (threadIdx.x < B_ * E_) gs[threadIdx.x] = ((const float*)g_gate)[threadIdx.x];
    __syncthreads();
    const float4* b4 = (const float4*)base;
    const float4* t4 = (const float4*)tv;
    float4* o4 = (float4*)out;
    for (long i = (long)blockIdx.x * blockDim.x + threadIdx.x; i < n4;
         i += (long)gridDim.x * blockDim.x) {
        float4 t[E_];
#pragma unroll
        for (int e = 0; e < E_; e++) t[e] = t4[(long)e * n4 + i];
        float4 bb = b4[i];
#pragma unroll
        for (int b = 0; b < B_; b++) {
            float4 o = bb;
#pragma unroll
            for (int e = 0; e < E_; e++) {
                float ge = gs[b * E_ + e];
                o.x += ge * t[e].x; o.y += ge * t[e].y;
                o.z += ge * t[e].z; o.w += ge * t[e].w;
            }
            if (docvt) { o.x = rtf(o.x); o.y = rtf(o.y); o.z = rtf(o.z); o.w = rtf(o.w); }
            o4[(long)b * n4 + i] = o;
        }
    }
}

// ---------------- LN param merge (gate-independent) --------------------------
__global__ void ln_merge(const float* __restrict__ lg, const float* __restrict__ lb,
                         const float* __restrict__ tg, const float* __restrict__ tb)
{
    int d = blockIdx.x * blockDim.x + threadIdx.x;
    if (d >= D_) return;
    float sg = 0.f, sb = 0.f;
#pragma unroll
    for (int e = 0; e < E_; e++) { sg += tg[e * D_ + d]; sb += tb[e * D_ + d]; }
    g_lng[d] = lg[d] + 0.03f * (sg - (float)E_ * lg[d]);
    g_lnb[d] = lb[d] + 0.03f * (sb - (float)E_ * lb[d]);
}

// ---------------- residual + layernorm (in-place on d_out) ------------------
__global__ void ln_kernel(const float* __restrict__ x, float* __restrict__ out)
{
    long row = blockIdx.x;
    const float* xr = x + row * (long)D_;
    float* orow = out + row * (long)D_;
    int t = threadIdx.x;
    float v0 = xr[t] + orow[t];
    float v1 = xr[t + 256] + orow[t + 256];
    float s = v0 + v1, q = v0 * v0 + v1 * v1;
#pragma unroll
    for (int off = 16; off; off >>= 1) {
        s += __shfl_xor_sync(0xffffffffu, s, off);
        q += __shfl_xor_sync(0xffffffffu, q, off);
    }
    __shared__ float ss[8], sq[8];
    __shared__ float smu, sinv;
    int w = t >> 5, l = t & 31;
    if (l == 0) { ss[w] = s; sq[w] = q; }
    __syncthreads();
    if (t == 0) {
        float S = 0.f, Q = 0.f;
#pragma unroll
        for (int i = 0; i < 8; i++) { S += ss[i]; Q += sq[i]; }
        float mu = S * (1.f / (float)D_);
        float var = Q * (1.f / (float)D_) - mu * mu;
        smu = mu;
        sinv = rsqrtf(var + 1e-5f);
    }
    __syncthreads();
    float mu = smu, inv = sinv;
    orow[t]       = (v0 - mu) * inv * g_lng[t]       + g_lnb[t];
    orow[t + 256] = (v1 - mu) * inv * g_lng[t + 256] + g_lnb[t + 256];
}

// ---------------- launch ------------------------------------------------------
extern "C" void kernel_launch(void* const* d_in, const int* in_sizes, int n_in,
                              void* d_out, int out_size)
{
    const float* x      = (const float*)d_in[0];
    const float* gfc1_w = (const float*)d_in[1];
    const float* gfc1_b = (const float*)d_in[2];
    const float* gfc2_w = (const float*)d_in[3];
    const float* gfc2_b = (const float*)d_in[4];
    const float* W1     = (const float*)d_in[5];
    const float* b1     = (const float*)d_in[6];
    const float* W2     = (const float*)d_in[7];
    const float* b2     = (const float*)d_in[8];
    const float* ln_g   = (const float*)d_in[9];
    const float* ln_b   = (const float*)d_in[10];
    const float* tv_W1  = (const float*)d_in[11];
    const float* tv_b1  = (const float*)d_in[12];
    const float* tv_W2  = (const float*)d_in[13];
    const float* tv_b2  = (const float*)d_in[14];
    const float* tv_lng = (const float*)d_in[15];
    const float* tv_lnb = (const float*)d_in[16];
    float* out = (float*)d_out;

    float *H, *xc, *gw1c, *W1m, *b1m, *W2m, *b2m;
    cudaGetSymbolAddress((void**)&H,    g_H);
    cudaGetSymbolAddress((void**)&xc,   g_xc);
    cudaGetSymbolAddress((void**)&gw1c, g_gw1c);
    cudaGetSymbolAddress((void**)&W1m,  g_W1m);
    cudaGetSymbolAddress((void**)&b1m,  g_b1m);
    cudaGetSymbolAddress((void**)&W2m,  g_W2m);
    cudaGetSymbolAddress((void**)&b2m,  g_b2m);

    const int smem = STAGES * STAGE_WORDS * 4;  // 96 KB
    cudaFuncSetAttribute(gemm_tf32<true,  false>, cudaFuncAttributeMaxDynamicSharedMemorySize, smem);
    cudaFuncSetAttribute(gemm_tf32<true,  true >, cudaFuncAttributeMaxDynamicSharedMemorySize, smem);
    cudaFuncSetAttribute(gemm_tf32<false, false>, cudaFuncAttributeMaxDynamicSharedMemorySize, smem);

    // 0) pre-round MMA operands to tf32 (RNA) so cp.async can copy raw bits
    cvt_kernel<<<2048, 256>>>((const float4*)x, (float4*)xc, (long)B_ * S_ * D_ / 4);
    cvt_kernel<<<128, 256>>>((const float4*)gfc1_w, (float4*)gw1c, (long)D_ * D_ / 4);

    // 1) gate fc1: gh = relu(xc @ gw1c^T + b)   [32768, 512] -> H
    gemm_tf32<true, false><<<dim3(D_ / BN, (B_ * S_) / BM, 1), 256, smem>>>(
        xc, 0, gw1c, 0, gfc1_b, 0, H, 0, B_ * S_, D_, D_);

    // 2) column sums + fc2 + mean -> g[b][e]
    gate_colsum<<<dim3(NSPLIT, B_), D_>>>(H);
    gate_fc2<<<B_, 256>>>(gfc2_w, gfc2_b);

    // 3) merged per-batch weights (tf32-rounded) / biases / LN params
    merge_kernel<<<512, 256>>>(W1, tv_W1, W1m, (F_ * D_) / 4, 1);
    merge_kernel<<<512, 256>>>(W2, tv_W2, W2m, (D_ * F_) / 4, 1);
    merge_kernel<<<4,   256>>>(b1, tv_b1, b1m, F_ / 4, 0);
    merge_kernel<<<2,   256>>>(b2, tv_b2, b2m, D_ / 4, 0);
    ln_merge<<<2, 256>>>(ln_g, ln_b, tv_lng, tv_lnb);

    // 4) FFN1: H_b = tf32(relu(xc_b @ W1m_b^T + b1m_b))   [4096, 2048] x 8
    gemm_tf32<true, true><<<dim3(F_ / BN, S_ / BM, B_), 256, smem>>>(
        xc, (long)S_ * D_, W1m, (long)F_ * D_, b1m, F_,
        H, (long)S_ * F_, S_, F_, D_);

    // 5) FFN2: out_b = H_b @ W2m_b^T + b2m_b              [4096, 512] x 8 (pre-LN)
    gemm_tf32<false, false><<<dim3(D_ / BN, S_ / BM, B_), 256, smem>>>(
        H, (long)S_ * F_, W2m, (long)D_ * F_, b2m, D_,
        out, (long)S_ * D_, S_, D_, F_);

    // 6) residual + layernorm, in place on d_out
    ln_kernel<<<B_ * S_, 256>>>(x, out);
}

// round 11
// speedup vs baseline: 1.3887x; 1.0035x over previous
#include <cuda_runtime.h>

#define B_ 8
#define S_ 4096
#define D_ 512
#define F_ 2048
#define E_ 8
#define NSPLIT 32

// ---------------- scratch (device globals; no allocation allowed) ----------
__device__ float g_H[(size_t)B_ * S_ * F_];          // gh (first 64MB) then FFN hidden (tf32-rounded)
__device__ float g_xc[(size_t)B_ * S_ * D_];         // x pre-rounded to tf32
__device__ float g_gw1c[D_ * D_];                    // gfc1_w pre-rounded to tf32
__device__ float g_ghpart[B_][NSPLIT][D_];
__device__ float g_gate[B_][E_];
__device__ float g_W1m[(size_t)B_ * F_ * D_];        // merged W1 (tf32-rounded)
__device__ float g_b1m[B_ * F_];
__device__ float g_W2m[(size_t)B_ * D_ * F_];        // merged W2 (tf32-rounded)
__device__ float g_b2m[B_ * D_];
__device__ float g_lng[D_];
__device__ float g_lnb[D_];

// ---------------- tf32 helpers ---------------------------------------------
__device__ __forceinline__ unsigned f2tf(float x) {
    unsigned u;
    asm("cvt.rna.tf32.f32 %0, %1;" : "=r"(u) : "f"(x));
    return u;
}
__device__ __forceinline__ float rtf(float x) { return __uint_as_float(f2tf(x)); }

// ---------------- pipelined tf32 tensor-core GEMM --------------------------
// C[M,N] = act(A[M,K] @ B[N,K]^T + bias[N]); A,B already tf32-rounded fp32.
// BM=BN=128, BK=32, 256 thr (8 warps 2x4), warp tile 64x32, 4x4 m16n8k8.
// 3-stage cp.async pipeline, XOR-swizzled smem (conflict-free ld & st).
#define BM 128
#define BN 128
#define BK 32
#define STAGES 3
#define STAGE_WORDS (2 * BM * BK)   // As + Bs per stage (8192 words = 32KB)

template <bool RELU, bool CVT>
__global__ void __launch_bounds__(256, 2)
gemm_tf32(const float* __restrict__ A, long sAb,
          const float* __restrict__ Bw, long sBb,
          const float* __restrict__ bias, long sBias,
          float* __restrict__ C, long sC,
          int M, int N, int K)
{
    extern __shared__ unsigned sm[];

    const int bz = blockIdx.z;
    A  += (long)bz * sAb;
    Bw += (long)bz * sBb;
    C  += (long)bz * sC;
    const float* bvec = bias + (long)bz * sBias;

    const int m0 = blockIdx.y * BM;
    const int n0 = blockIdx.x * BN;

    const int tid  = threadIdx.x;
    const int warp = tid >> 5;
    const int lane = tid & 31;
    const int gid  = lane >> 2;
    const int tig  = lane & 3;
    const int wm   = warp >> 2;   // 0..1
    const int wn   = warp & 3;    // 0..3

    float acc[4][4][4];
#pragma unroll
    for (int i = 0; i < 4; i++)
#pragma unroll
        for (int j = 0; j < 4; j++)
#pragma unroll
            for (int q = 0; q < 4; q++) acc[i][j][q] = 0.f;

    const int KT = K / BK;

    // per-thread load coords: idx = tid + it*256 -> r = idx>>3, chunk c8 = idx&7
    auto load_stage = [&](int st, int kt) {
        unsigned* As = sm + st * STAGE_WORDS;
        unsigned* Bs = As + BM * BK;
#pragma unroll
        for (int it = 0; it < 4; it++) {
            int idx = tid + it * 256;
            int r = idx >> 3, c8 = idx & 7;
            int dst = r * BK + ((c8 ^ (r & 7)) << 2);
            unsigned sa = (unsigned)__cvta_generic_to_shared(As + dst);
            asm volatile("cp.async.cg.shared.global [%0], [%1], 16;\n"
                         :: "r"(sa), "l"(A + (long)(m0 + r) * K + kt + c8 * 4));
            unsigned sb = (unsigned)__cvta_generic_to_shared(Bs + dst);
            asm volatile("cp.async.cg.shared.global [%0], [%1], 16;\n"
                         :: "r"(sb), "l"(Bw + (long)(n0 + r) * K + kt + c8 * 4));
        }
    };

#pragma unroll
    for (int s = 0; s < STAGES - 1; s++) {
        load_stage(s, s * BK);
        asm volatile("cp.async.commit_group;\n");
    }

    for (int i = 0; i < KT; i++) {
        asm volatile("cp.async.wait_group %0;\n" :: "n"(STAGES - 2));
        __syncthreads();

        int nxt = i + STAGES - 1;
        if (nxt < KT) load_stage(nxt % STAGES, nxt * BK);
        asm volatile("cp.async.commit_group;\n");

        const unsigned* As = sm + (i % STAGES) * STAGE_WORDS;
        const unsigned* Bs = As + BM * BK;

#pragma unroll
        for (int kk = 0; kk < BK; kk += 8) {
            const int k4 = kk >> 2;
            unsigned af[4][4], bf[4][2];
            const int sw0 = ((k4 ^ gid) << 2) + tig;
            const int sw1 = (((k4 + 1) ^ gid) << 2) + tig;
#pragma unroll
            for (int mf = 0; mf < 4; mf++) {
                int r0 = (wm * 64 + mf * 16 + gid) * BK;
                af[mf][0] = As[r0 + sw0];
                af[mf][1] = As[r0 + 8 * BK + sw0];
                af[mf][2] = As[r0 + sw1];
                af[mf][3] = As[r0 + 8 * BK + sw1];
            }
#pragma unroll
            for (int nf = 0; nf < 4; nf++) {
                int nr = (wn * 32 + nf * 8 + gid) * BK;
                bf[nf][0] = Bs[nr + sw0];
                bf[nf][1] = Bs[nr + sw1];
            }
#pragma unroll
            for (int mf = 0; mf < 4; mf++)
#pragma unroll
                for (int nf = 0; nf < 4; nf++) {
                    asm volatile(
                        "mma.sync.aligned.m16n8k8.row.col.f32.tf32.tf32.f32 "
                        "{%0,%1,%2,%3}, {%4,%5,%6,%7}, {%8,%9}, {%0,%1,%2,%3};\n"
                        : "+f"(acc[mf][nf][0]), "+f"(acc[mf][nf][1]),
                          "+f"(acc[mf][nf][2]), "+f"(acc[mf][nf][3])
                        : "r"(af[mf][0]), "r"(af[mf][1]),
                          "r"(af[mf][2]), "r"(af[mf][3]),
                          "r"(bf[nf][0]), "r"(bf[nf][1]));
                }
        }
    }

    // epilogue: bias (+relu) (+tf32 rounding), float2 stores
#pragma unroll
    for (int mf = 0; mf < 4; mf++) {
        int r0 = m0 + wm * 64 + mf * 16 + gid;
#pragma unroll
        for (int nf = 0; nf < 4; nf++) {
            int c0 = n0 + wn * 32 + nf * 8 + 2 * tig;
            float bb0 = bvec[c0];
            float bb1 = bvec[c0 + 1];
            float v0 = acc[mf][nf][0] + bb0;
            float v1 = acc[mf][nf][1] + bb1;
            float v2 = acc[mf][nf][2] + bb0;
            float v3 = acc[mf][nf][3] + bb1;
            if (RELU) {
                v0 = fmaxf(v0, 0.f); v1 = fmaxf(v1, 0.f);
                v2 = fmaxf(v2, 0.f); v3 = fmaxf(v3, 0.f);
            }
            if (CVT) { v0 = rtf(v0); v1 = rtf(v1); v2 = rtf(v2); v3 = rtf(v3); }
            *(float2*)(C + (long)r0 * N + c0)       = make_float2(v0, v1);
            *(float2*)(C + (long)(r0 + 8) * N + c0) = make_float2(v2, v3);
        }
    }
}

// ---------------- tf32 pre-rounding copy ------------------------------------
__global__ void cvt_kernel(const float4* __restrict__ in, float4* __restrict__ out, long n4)
{
    for (long i = (long)blockIdx.x * blockDim.x + threadIdx.x; i < n4;
         i += (long)gridDim.x * blockDim.x) {
        float4 v = in[i];
        v.x = rtf(v.x); v.y = rtf(v.y); v.z = rtf(v.z); v.w = rtf(v.w);
        out[i] = v;
    }
}

// ---------------- gate: column sum of gh over tokens ------------------------
__global__ void gate_colsum(const float* __restrict__ gh)
{
    int sp = blockIdx.x, b = blockIdx.y, h = threadIdx.x;
    const int chunk = S_ / NSPLIT;
    const float* p = gh + ((long)b * S_ + (long)sp * chunk) * D_ + h;
    float s = 0.f;
#pragma unroll 8
    for (int i = 0; i < chunk; i++) s += p[(long)i * D_];
    g_ghpart[b][sp][h] = s;
}

// ---------------- gate: fc2 + mean ------------------------------------------
__global__ void gate_fc2(const float* __restrict__ g2w, const float* __restrict__ g2b)
{
    __shared__ float hs[D_];
    int b = blockIdx.x;
    for (int h = threadIdx.x; h < D_; h += 256) {
        float s = 0.f;
#pragma unroll
        for (int p = 0; p < NSPLIT; p++) s += g_ghpart[b][p][h];
        hs[h] = s;
    }
    __syncthreads();
    int w = threadIdx.x >> 5, l = threadIdx.x & 31;
    float s = 0.f;
    for (int h = l; h < D_; h += 32) s += hs[h] * g2w[w * D_ + h];
#pragma unroll
    for (int off = 16; off; off >>= 1) s += __shfl_xor_sync(0xffffffffu, s, off);
    if (l == 0) g_gate[b][w] = g2b[w] + s * (1.f / (float)S_);
}

// ---------------- merge: out[b][i] = base[i] + sum_e g[b][e]*tv[e][i] --------
__global__ void merge_kernel(const float* __restrict__ base, const float* __restrict__ tv,
                             float* __restrict__ out, int n4, int docvt)
{
    __shared__ float gs[B_ * E_];
    if (threadIdx.x < B_ * E_) gs[threadIdx.x] = ((const float*)g_gate)[threadIdx.x];
    __syncthreads();
    const float4* b4 = (const float4*)base;
    const float4* t4 = (const float4*)tv;
    float4* o4 = (float4*)out;
    for (long i = (long)blockIdx.x * blockDim.x + threadIdx.x; i < n4;
         i += (long)gridDim.x * blockDim.x) {
        float4 t[E_];
#pragma unroll
        for (int e = 0; e < E_; e++) t[e] = t4[(long)e * n4 + i];
        float4 bb = b4[i];
#pragma unroll
        for (int b = 0; b < B_; b++) {
            float4 o = bb;
#pragma unroll
            for (int e = 0; e < E_; e++) {
                float ge = gs[b * E_ + e];
                o.x += ge * t[e].x; o.y += ge * t[e].y;
                o.z += ge * t[e].z; o.w += ge * t[e].w;
            }
            if (docvt) { o.x = rtf(o.x); o.y = rtf(o.y); o.z = rtf(o.z); o.w = rtf(o.w); }
            o4[(long)b * n4 + i] = o;
        }
    }
}

// ---------------- LN param merge (gate-independent) --------------------------
__global__ void ln_merge(const float* __restrict__ lg, const float* __restrict__ lb,
                         const float* __restrict__ tg, const float* __restrict__ tb)
{
    int d = blockIdx.x * blockDim.x + threadIdx.x;
    if (d >= D_) return;
    float sg = 0.f, sb = 0.f;
#pragma unroll
    for (int e = 0; e < E_; e++) { sg += tg[e * D_ + d]; sb += tb[e * D_ + d]; }
    g_lng[d] = lg[d] + 0.03f * (sg - (float)E_ * lg[d]);
    g_lnb[d] = lb[d] + 0.03f * (sb - (float)E_ * lb[d]);
}

// ---------------- residual + layernorm (in-place on d_out) ------------------
__global__ void ln_kernel(const float* __restrict__ x, float* __restrict__ out)
{
    long row = blockIdx.x;
    const float* xr = x + row * (long)D_;
    float* orow = out + row * (long)D_;
    int t = threadIdx.x;
    float v0 = xr[t] + orow[t];
    float v1 = xr[t + 256] + orow[t + 256];
    float s = v0 + v1, q = v0 * v0 + v1 * v1;
#pragma unroll
    for (int off = 16; off; off >>= 1) {
        s += __shfl_xor_sync(0xffffffffu, s, off);
        q += __shfl_xor_sync(0xffffffffu, q, off);
    }
    __shared__ float ss[8], sq[8];
    __shared__ float smu, sinv;
    int w = t >> 5, l = t & 31;
    if (l == 0) { ss[w] = s; sq[w] = q; }
    __syncthreads();
    if (t == 0) {
        float S = 0.f, Q = 0.f;
#pragma unroll
        for (int i = 0; i < 8; i++) { S += ss[i]; Q += sq[i]; }
        float mu = S * (1.f / (float)D_);
        float var = Q * (1.f / (float)D_) - mu * mu;
        smu = mu;
        sinv = rsqrtf(var + 1e-5f);
    }
    __syncthreads();
    float mu = smu, inv = sinv;
    orow[t]       = (v0 - mu) * inv * g_lng[t]       + g_lnb[t];
    orow[t + 256] = (v1 - mu) * inv * g_lng[t + 256] + g_lnb[t + 256];
}

// ---------------- launch ------------------------------------------------------
extern "C" void kernel_launch(void* const* d_in, const int* in_sizes, int n_in,
                              void* d_out, int out_size)
{
    const float* x      = (const float*)d_in[0];
    const float* gfc1_w = (const float*)d_in[1];
    const float* gfc1_b = (const float*)d_in[2];
    const float* gfc2_w = (const float*)d_in[3];
    const float* gfc2_b = (const float*)d_in[4];
    const float* W1     = (const float*)d_in[5];
    const float* b1     = (const float*)d_in[6];
    const float* W2     = (const float*)d_in[7];
    const float* b2     = (const float*)d_in[8];
    const float* ln_g   = (const float*)d_in[9];
    const float* ln_b   = (const float*)d_in[10];
    const float* tv_W1  = (const float*)d_in[11];
    const float* tv_b1  = (const float*)d_in[12];
    const float* tv_W2  = (const float*)d_in[13];
    const float* tv_b2  = (const float*)d_in[14];
    const float* tv_lng = (const float*)d_in[15];
    const float* tv_lnb = (const float*)d_in[16];
    float* out = (float*)d_out;

    float *H, *xc, *gw1c, *W1m, *b1m, *W2m, *b2m;
    cudaGetSymbolAddress((void**)&H,    g_H);
    cudaGetSymbolAddress((void**)&xc,   g_xc);
    cudaGetSymbolAddress((void**)&gw1c, g_gw1c);
    cudaGetSymbolAddress((void**)&W1m,  g_W1m);
    cudaGetSymbolAddress((void**)&b1m,  g_b1m);
    cudaGetSymbolAddress((void**)&W2m,  g_W2m);
    cudaGetSymbolAddress((void**)&b2m,  g_b2m);

    const int smem = STAGES * STAGE_WORDS * 4;  // 96 KB
    cudaFuncSetAttribute(gemm_tf32<true,  false>, cudaFuncAttributeMaxDynamicSharedMemorySize, smem);
    cudaFuncSetAttribute(gemm_tf32<true,  true >, cudaFuncAttributeMaxDynamicSharedMemorySize, smem);
    cudaFuncSetAttribute(gemm_tf32<false, false>, cudaFuncAttributeMaxDynamicSharedMemorySize, smem);

    // 0) pre-round MMA operands to tf32 (RNA) so cp.async can copy raw bits
    cvt_kernel<<<2048, 256>>>((const float4*)x, (float4*)xc, (long)B_ * S_ * D_ / 4);
    cvt_kernel<<<128, 256>>>((const float4*)gfc1_w, (float4*)gw1c, (long)D_ * D_ / 4);

    // 1) gate fc1: gh = relu(xc @ gw1c^T + b)   [32768, 512] -> H
    gemm_tf32<true, false><<<dim3(D_ / BN, (B_ * S_) / BM, 1), 256, smem>>>(
        xc, 0, gw1c, 0, gfc1_b, 0, H, 0, B_ * S_, D_, D_);

    // 2) column sums + fc2 + mean -> g[b][e]
    gate_colsum<<<dim3(NSPLIT, B_), D_>>>(H);
    gate_fc2<<<B_, 256>>>(gfc2_w, gfc2_b);

    // 3) merged per-batch weights (tf32-rounded) / biases / LN params
    merge_kernel<<<512, 256>>>(W1, tv_W1, W1m, (F_ * D_) / 4, 1);
    merge_kernel<<<512, 256>>>(W2, tv_W2, W2m, (D_ * F_) / 4, 1);
    merge_kernel<<<4,   256>>>(b1, tv_b1, b1m, F_ / 4, 0);
    merge_kernel<<<2,   256>>>(b2, tv_b2, b2m, D_ / 4, 0);
    ln_merge<<<2, 256>>>(ln_g, ln_b, tv_lng, tv_lnb);

    // 4) FFN1: H_b = tf32(relu(xc_b @ W1m_b^T + b1m_b))   [4096, 2048] x 8
    gemm_tf32<true, true><<<dim3(F_ / BN, S_ / BM, B_), 256, smem>>>(
        xc, (long)S_ * D_, W1m, (long)F_ * D_, b1m, F_,
        H, (long)S_ * F_, S_, F_, D_);

    // 5) FFN2: out_b = H_b @ W2m_b^T + b2m_b              [4096, 512] x 8 (pre-LN)
    gemm_tf32<false, false><<<dim3(D_ / BN, S_ / BM, B_), 256, smem>>>(
        H, (long)S_ * F_, W2m, (long)D_ * F_, b2m, D_,
        out, (long)S_ * D_, S_, D_, F_);

    // 6) residual + layernorm, in place on d_out
    ln_kernel<<<B_ * S_, 256>>>(x, out);
}

// round 14
// speedup vs baseline: 2.3756x; 1.7107x over previous
#include <cuda_runtime.h>
#include <cuda_fp16.h>
#include <cstdint>

#define B_ 8
#define S_ 4096
#define D_ 512
#define F_ 2048
#define E_ 8
#define NSPLIT 32

// ---------------- scratch (device globals; no allocation allowed) ----------
__device__ __half g_xh[(size_t)B_ * S_ * D_];        // x in fp16
__device__ __half g_gw1h[D_ * D_];                   // gfc1_w in fp16
__device__ __half g_gh[(size_t)B_ * S_ * D_];        // gate hidden (fp16)
__device__ __half g_Hh[(size_t)B_ * S_ * F_];        // FFN hidden (fp16)
__device__ __half g_W1h[(size_t)B_ * F_ * D_];       // merged W1 (fp16)
__device__ __half g_W2h[(size_t)B_ * D_ * F_];       // merged W2 (fp16)
__device__ float g_ghpart[B_][NSPLIT][D_];
__device__ float g_gate[B_][E_];
__device__ float g_b1m[B_ * F_];
__device__ float g_b2m[B_ * D_];
__device__ float g_lng[D_];
__device__ float g_lnb[D_];

// ---------------- pipelined fp16 tensor-core GEMM ---------------------------
// C[M,N] = act(A[M,K] @ B[N,K]^T + bias[N]); A,B fp16 K-major, fp32 accumulate.
// BM=BN=128, BK=64 halves (128B rows), 256 thr (8 warps 2x4), warp tile 64x32,
// 4x4 m16n8k16 fragments, 3-stage cp.async ring, XOR-swizzled smem.
#define BM 128
#define BN 128
#define BKE 64
#define STAGES 3
#define STAGE_WORDS (2 * BM * 32)   // A(4096 words) + B(4096 words) per stage

template <bool RELU, typename OutT>
__global__ void __launch_bounds__(256, 2)
gemm_f16(const __half* __restrict__ A, long sAb,
         const __half* __restrict__ Bw, long sBb,
         const float* __restrict__ bias, long sBias,
         OutT* __restrict__ C, long sC,
         int M, int N, int K)
{
    extern __shared__ unsigned sm[];

    const int bz = blockIdx.z;
    A  += (long)bz * sAb;
    Bw += (long)bz * sBb;
    C  += (long)bz * sC;
    const float* bvec = bias + (long)bz * sBias;

    const int m0 = blockIdx.y * BM;
    const int n0 = blockIdx.x * BN;

    const int tid  = threadIdx.x;
    const int warp = tid >> 5;
    const int lane = tid & 31;
    const int gid  = lane >> 2;
    const int tig  = lane & 3;
    const int wm   = warp >> 2;   // 0..1
    const int wn   = warp & 3;    // 0..3

    float acc[4][4][4];
#pragma unroll
    for (int i = 0; i < 4; i++)
#pragma unroll
        for (int j = 0; j < 4; j++)
#pragma unroll
            for (int q = 0; q < 4; q++) acc[i][j][q] = 0.f;

    const int KT = K / BKE;

    // stage layout: A rows [0,128) then B rows [0,128), 32 words (128B) per row,
    // 16B chunks XOR-swizzled by row&7.
    auto load_stage = [&](int st, int kt) {
        unsigned* As = sm + st * STAGE_WORDS;
        unsigned* Bs = As + BM * 32;
#pragma unroll
        for (int it = 0; it < 8; it++) {
            int idx = tid + it * 256;             // 0..2047 chunks
            const bool isA = (it < 4);
            int loc = isA ? idx : idx - 1024;
            int r = loc >> 3, c8 = loc & 7;
            unsigned* base = isA ? As : Bs;
            unsigned dst = (unsigned)__cvta_generic_to_shared(
                base + r * 32 + ((c8 ^ (r & 7)) << 2));
            const __half* src = (isA ? A + (long)(m0 + r) * K
                                     : Bw + (long)(n0 + r) * K) + kt + c8 * 8;
            asm volatile("cp.async.cg.shared.global [%0], [%1], 16;\n"
                         :: "r"(dst), "l"(src));
        }
    };

#pragma unroll
    for (int s = 0; s < STAGES - 1; s++) {
        load_stage(s, s * BKE);
        asm volatile("cp.async.commit_group;\n");
    }

    for (int i = 0; i < KT; i++) {
        asm volatile("cp.async.wait_group %0;\n" :: "n"(STAGES - 2));
        __syncthreads();

        int nxt = i + STAGES - 1;
        if (nxt < KT) load_stage(nxt % STAGES, nxt * BKE);
        asm volatile("cp.async.commit_group;\n");

        const unsigned* As = sm + (i % STAGES) * STAGE_WORDS;
        const unsigned* Bs = As + BM * 32;

#pragma unroll
        for (int g = 0; g < 4; g++) {            // four k16 groups per stage
            unsigned af[4][4], bf[4][2];
            const int sw0 = (((2 * g)     ^ gid) << 2) + tig;
            const int sw1 = (((2 * g + 1) ^ gid) << 2) + tig;
#pragma unroll
            for (int mf = 0; mf < 4; mf++) {
                int r0 = (wm * 64 + mf * 16 + gid) * 32;
                af[mf][0] = As[r0 + sw0];
                af[mf][1] = As[r0 + 8 * 32 + sw0];
                af[mf][2] = As[r0 + sw1];
                af[mf][3] = As[r0 + 8 * 32 + sw1];
            }
#pragma unroll
            for (int nf = 0; nf < 4; nf++) {
                int nr = (wn * 32 + nf * 8 + gid) * 32;
                bf[nf][0] = Bs[nr + sw0];
                bf[nf][1] = Bs[nr + sw1];
            }
#pragma unroll
            for (int mf = 0; mf < 4; mf++)
#pragma unroll
                for (int nf = 0; nf < 4; nf++) {
                    asm volatile(
                        "mma.sync.aligned.m16n8k16.row.col.f32.f16.f16.f32 "
                        "{%0,%1,%2,%3}, {%4,%5,%6,%7}, {%8,%9}, {%0,%1,%2,%3};\n"
                        : "+f"(acc[mf][nf][0]), "+f"(acc[mf][nf][1]),
                          "+f"(acc[mf][nf][2]), "+f"(acc[mf][nf][3])
                        : "r"(af[mf][0]), "r"(af[mf][1]),
                          "r"(af[mf][2]), "r"(af[mf][3]),
                          "r"(bf[nf][0]), "r"(bf[nf][1]));
                }
        }
    }

    // epilogue: bias (+relu), float2 or half2 stores
#pragma unroll
    for (int mf = 0; mf < 4; mf++) {
        int r0 = m0 + wm * 64 + mf * 16 + gid;
#pragma unroll
        for (int nf = 0; nf < 4; nf++) {
            int c0 = n0 + wn * 32 + nf * 8 + 2 * tig;
            float bb0 = bvec[c0];
            float bb1 = bvec[c0 + 1];
            float v0 = acc[mf][nf][0] + bb0;
            float v1 = acc[mf][nf][1] + bb1;
            float v2 = acc[mf][nf][2] + bb0;
            float v3 = acc[mf][nf][3] + bb1;
            if (RELU) {
                v0 = fmaxf(v0, 0.f); v1 = fmaxf(v1, 0.f);
                v2 = fmaxf(v2, 0.f); v3 = fmaxf(v3, 0.f);
            }
            if constexpr (sizeof(OutT) == 4) {
                *(float2*)((float*)C + (long)r0 * N + c0)       = make_float2(v0, v1);
                *(float2*)((float*)C + (long)(r0 + 8) * N + c0) = make_float2(v2, v3);
            } else {
                *(__half2*)((__half*)C + (long)r0 * N + c0)       = __floats2half2_rn(v0, v1);
                *(__half2*)((__half*)C + (long)(r0 + 8) * N + c0) = __floats2half2_rn(v2, v3);
            }
        }
    }
}

// ---------------- fp32 -> fp16 copy -----------------------------------------
__global__ void cvt_h(const float4* __restrict__ in, __half* __restrict__ out, long n4)
{
    for (long i = (long)blockIdx.x * blockDim.x + threadIdx.x; i < n4;
         i += (long)gridDim.x * blockDim.x) {
        float4 v = in[i];
        __half2 lo = __floats2half2_rn(v.x, v.y);
        __half2 hi = __floats2half2_rn(v.z, v.w);
        uint2 u;
        u.x = *(unsigned*)&lo;
        u.y = *(unsigned*)&hi;
        ((uint2*)out)[i] = u;
    }
}

// ---------------- gate: column sum of gh over tokens ------------------------
__global__ void gate_colsum(const __half* __restrict__ gh)
{
    int sp = blockIdx.x, b = blockIdx.y, h = threadIdx.x;
    const int chunk = S_ / NSPLIT;
    const __half* p = gh + ((long)b * S_ + (long)sp * chunk) * D_ + h;
    float s = 0.f;
#pragma unroll 8
    for (int i = 0; i < chunk; i++) s += __half2float(p[(long)i * D_]);
    g_ghpart[b][sp][h] = s;
}

// ---------------- gate: fc2 + mean ------------------------------------------
__global__ void gate_fc2(const float* __restrict__ g2w, const float* __restrict__ g2b)
{
    __shared__ float hs[D_];
    int b = blockIdx.x;
    for (int h = threadIdx.x; h < D_; h += 256) {
        float s = 0.f;
#pragma unroll
        for (int p = 0; p < NSPLIT; p++) s += g_ghpart[b][p][h];
        hs[h] = s;
    }
    __syncthreads();
    int w = threadIdx.x >> 5, l = threadIdx.x & 31;
    float s = 0.f;
    for (int h = l; h < D_; h += 32) s += hs[h] * g2w[w * D_ + h];
#pragma unroll
    for (int off = 16; off; off >>= 1) s += __shfl_xor_sync(0xffffffffu, s, off);
    if (l == 0) g_gate[b][w] = g2b[w] + s * (1.f / (float)S_);
}

// ---------------- merge W: half out -----------------------------------------
__global__ void merge_w_kernel(const float* __restrict__ base, const float* __restrict__ tv,
                               __half* __restrict__ out, int n4)
{
    __shared__ float gs[B_ * E_];
    if (threadIdx.x < B_ * E_) gs[threadIdx.x] = ((const float*)g_gate)[threadIdx.x];
    __syncthreads();
    const float4* b4 = (const float4*)base;
    const float4* t4 = (const float4*)tv;
    uint2* o4 = (uint2*)out;
    for (long i = (long)blockIdx.x * blockDim.x + threadIdx.x; i < n4;
         i += (long)gridDim.x * blockDim.x) {
        float4 t[E_];
#pragma unroll
        for (int e = 0; e < E_; e++) t[e] = t4[(long)e * n4 + i];
        float4 bb = b4[i];
#pragma unroll
        for (int b = 0; b < B_; b++) {
            float4 o = bb;
#pragma unroll
            for (int e = 0; e < E_; e++) {
                float ge = gs[b * E_ + e];
                o.x += ge * t[e].x; o.y += ge * t[e].y;
                o.z += ge * t[e].z; o.w += ge * t[e].w;
            }
            __half2 lo = __floats2half2_rn(o.x, o.y);
            __half2 hi = __floats2half2_rn(o.z, o.w);
            uint2 u;
            u.x = *(unsigned*)&lo;
            u.y = *(unsigned*)&hi;
            o4[(long)b * n4 + i] = u;
        }
    }
}

// ---------------- merge bias: float out -------------------------------------
__global__ void merge_b_kernel(const float* __restrict__ base, const float* __restrict__ tv,
                               float* __restrict__ out, int n4)
{
    __shared__ float gs[B_ * E_];
    if (threadIdx.x < B_ * E_) gs[threadIdx.x] = ((const float*)g_gate)[threadIdx.x];
    __syncthreads();
    const float4* b4 = (const float4*)base;
    const float4* t4 = (const float4*)tv;
    float4* o4 = (float4*)out;
    for (long i = (long)blockIdx.x * blockDim.x + threadIdx.x; i < n4;
         i += (long)gridDim.x * blockDim.x) {
        float4 t[E_];
#pragma unroll
        for (int e = 0; e < E_; e++) t[e] = t4[(long)e * n4 + i];
        float4 bb = b4[i];
#pragma unroll
        for (int b = 0; b < B_; b++) {
            float4 o = bb;
#pragma unroll
            for (int e = 0; e < E_; e++) {
                float ge = gs[b * E_ + e];
                o.x += ge * t[e].x; o.y += ge * t[e].y;
                o.z += ge * t[e].z; o.w += ge * t[e].w;
            }
            o4[(long)b * n4 + i] = o;
        }
    }
}

// ---------------- LN param merge (gate-independent) --------------------------
__global__ void ln_merge(const float* __restrict__ lg, const float* __restrict__ lb,
                         const float* __restrict__ tg, const float* __restrict__ tb)
{
    int d = blockIdx.x * blockDim.x + threadIdx.x;
    if (d >= D_) return;
    float sg = 0.f, sb = 0.f;
#pragma unroll
    for (int e = 0; e < E_; e++) { sg += tg[e * D_ + d]; sb += tb[e * D_ + d]; }
    g_lng[d] = lg[d] + 0.03f * (sg - (float)E_ * lg[d]);
    g_lnb[d] = lb[d] + 0.03f * (sb - (float)E_ * lb[d]);
}

// ---------------- residual + layernorm (in-place on d_out) ------------------
__global__ void ln_kernel(const float* __restrict__ x, float* __restrict__ out)
{
    long row = blockIdx.x;
    const float* xr = x + row * (long)D_;
    float* orow = out + row * (long)D_;
    int t = threadIdx.x;
    float v0 = xr[t] + orow[t];
    float v1 = xr[t + 256] + orow[t + 256];
    float s = v0 + v1, q = v0 * v0 + v1 * v1;
#pragma unroll
    for (int off = 16; off; off >>= 1) {
        s += __shfl_xor_sync(0xffffffffu, s, off);
        q += __shfl_xor_sync(0xffffffffu, q, off);
    }
    __shared__ float ss[8], sq[8];
    __shared__ float smu, sinv;
    int w = t >> 5, l = t & 31;
    if (l == 0) { ss[w] = s; sq[w] = q; }
    __syncthreads();
    if (t == 0) {
        float S = 0.f, Q = 0.f;
#pragma unroll
        for (int i = 0; i < 8; i++) { S += ss[i]; Q += sq[i]; }
        float mu = S * (1.f / (float)D_);
        float var = Q * (1.f / (float)D_) - mu * mu;
        smu = mu;
        sinv = rsqrtf(var + 1e-5f);
    }
    __syncthreads();
    float mu = smu, inv = sinv;
    orow[t]       = (v0 - mu) * inv * g_lng[t]       + g_lnb[t];
    orow[t + 256] = (v1 - mu) * inv * g_lng[t + 256] + g_lnb[t + 256];
}

// ---------------- launch ------------------------------------------------------
extern "C" void kernel_launch(void* const* d_in, const int* in_sizes, int n_in,
                              void* d_out, int out_size)
{
    const float* x      = (const float*)d_in[0];
    const float* gfc1_w = (const float*)d_in[1];
    const float* gfc1_b = (const float*)d_in[2];
    const float* gfc2_w = (const float*)d_in[3];
    const float* gfc2_b = (const float*)d_in[4];
    const float* W1     = (const float*)d_in[5];
    const float* b1     = (const float*)d_in[6];
    const float* W2     = (const float*)d_in[7];
    const float* b2     = (const float*)d_in[8];
    const float* ln_g   = (const float*)d_in[9];
    const float* ln_b   = (const float*)d_in[10];
    const float* tv_W1  = (const float*)d_in[11];
    const float* tv_b1  = (const float*)d_in[12];
    const float* tv_W2  = (const float*)d_in[13];
    const float* tv_b2  = (const float*)d_in[14];
    const float* tv_lng = (const float*)d_in[15];
    const float* tv_lnb = (const float*)d_in[16];
    float* out = (float*)d_out;

    __half *xh, *gw1h, *gh, *Hh, *W1h, *W2h;
    float *b1m, *b2m;
    cudaGetSymbolAddress((void**)&xh,   g_xh);
    cudaGetSymbolAddress((void**)&gw1h, g_gw1h);
    cudaGetSymbolAddress((void**)&gh,   g_gh);
    cudaGetSymbolAddress((void**)&Hh,   g_Hh);
    cudaGetSymbolAddress((void**)&W1h,  g_W1h);
    cudaGetSymbolAddress((void**)&W2h,  g_W2h);
    cudaGetSymbolAddress((void**)&b1m,  g_b1m);
    cudaGetSymbolAddress((void**)&b2m,  g_b2m);

    const int smem = STAGES * STAGE_WORDS * 4;  // 96 KB
    cudaFuncSetAttribute(gemm_f16<true,  __half>, cudaFuncAttributeMaxDynamicSharedMemorySize, smem);
    cudaFuncSetAttribute(gemm_f16<false, float>,  cudaFuncAttributeMaxDynamicSharedMemorySize, smem);

    // 0) convert MMA operands to fp16
    cvt_h<<<2048, 256>>>((const float4*)x, xh, (long)B_ * S_ * D_ / 4);
    cvt_h<<<128, 256>>>((const float4*)gfc1_w, gw1h, (long)D_ * D_ / 4);

    // 1) gate fc1: gh = relu(xh @ gw1h^T + b)   [32768, 512] fp16 out
    gemm_f16<true, __half><<<dim3(D_ / BN, (B_ * S_) / BM, 1), 256, smem>>>(
        xh, 0, gw1h, 0, gfc1_b, 0, gh, 0, B_ * S_, D_, D_);

    // 2) column sums + fc2 + mean -> g[b][e]
    gate_colsum<<<dim3(NSPLIT, B_), D_>>>(gh);
    gate_fc2<<<B_, 256>>>(gfc2_w, gfc2_b);

    // 3) merged per-batch weights (fp16) / biases / LN params
    merge_w_kernel<<<512, 256>>>(W1, tv_W1, W1h, (F_ * D_) / 4);
    merge_w_kernel<<<512, 256>>>(W2, tv_W2, W2h, (D_ * F_) / 4);
    merge_b_kernel<<<4,   256>>>(b1, tv_b1, b1m, F_ / 4);
    merge_b_kernel<<<2,   256>>>(b2, tv_b2, b2m, D_ / 4);
    ln_merge<<<2, 256>>>(ln_g, ln_b, tv_lng, tv_lnb);

    // 4) FFN1: Hh_b = fp16(relu(xh_b @ W1h_b^T + b1m_b))   [4096, 2048] x 8
    gemm_f16<true, __half><<<dim3(F_ / BN, S_ / BM, B_), 256, smem>>>(
        xh, (long)S_ * D_, W1h, (long)F_ * D_, b1m, F_,
        Hh, (long)S_ * F_, S_, F_, D_);

    // 5) FFN2: out_b = Hh_b @ W2h_b^T + b2m_b              [4096, 512] x 8 (pre-LN)
    gemm_f16<false, float><<<dim3(D_ / BN, S_ / BM, B_), 256, smem>>>(
        Hh, (long)S_ * F_, W2h, (long)D_ * F_, b2m, D_,
        out, (long)S_ * D_, S_, D_, F_);

    // 6) residual + layernorm, in place on d_out
    ln_kernel<<<B_ * S_, 256>>>(x, out);
}